// round 11
// baseline (speedup 1.0000x reference)
#include <cuda_runtime.h>
#include <cuda_fp16.h>
#include <math.h>

#define NC   17
#define MAXB 8
#define FULL 0xffffffffu
#define SMAX 448

// z-pair scratch, up to 2 batches of 200*200*16 cells
#define PAD_CELL_CAP (2 * 640000)
// semantic: per cell 5 uint4 (80B): 17 x half2(v[z],v[z+1]) + pad
__device__ uint4  g_spair[(size_t)PAD_CELL_CAP * 5];
// density: per cell float2(d[z], d[z+1])
__device__ float2 g_dpair[PAD_CELL_CAP];

__device__ double g_wy[MAXB], g_wynll[MAXB], g_ent[MAXB], g_bi[MAXB], g_w2[MAXB];
__device__ unsigned long long g_pk[MAXB];
__device__ int g_nv[MAXB];

struct Params {
  float cw[NC];
  float cz;
  float bg, one_bg;
  float xminxy, invrngxy;
  float zminf, invrngz;
  float dist_thres, act_shift;
  int n_inner, n_outer, S;
  int N, B;
  int use_pad;
};

// Stages 16 (x,y)-columns (16 z * 17 ch = 272 floats each) through smem,
// emits z-pair interleaved fp16 rows + density float2 pairs.
// grid.x = ncols/16, block = 256 (one thread per cell of the 16 columns).
__global__ void __launch_bounds__(256)
nerf_prepass_kernel(const float* __restrict__ sem,
                    const float* __restrict__ dens) {
  __shared__ float sh[4352];   // 16 cols * 272 floats
  const int bid = blockIdx.x, tid = threadIdx.x;
  if (bid == 0 && tid < MAXB) {
    g_wy[tid] = 0.0; g_wynll[tid] = 0.0; g_ent[tid] = 0.0;
    g_bi[tid] = 0.0; g_w2[tid] = 0.0; g_pk[tid] = 0ull; g_nv[tid] = 0;
  }
  const size_t base = (size_t)bid * 4352;
  const float4* __restrict__ s4 = reinterpret_cast<const float4*>(sem + base);
  float4* sh4 = reinterpret_cast<float4*>(sh);
  #pragma unroll 4
  for (int i = tid; i < 1088; i += 256) sh4[i] = __ldg(s4 + i);
  __syncthreads();

  const int col = tid >> 4, z = tid & 15;
  const int gcell = bid * 256 + tid;      // = (bid*16+col)*16 + z
  const float* cv = sh + col * 272 + z * 17;
  const bool z1v = (z < 15);

  unsigned u[20];
  #pragma unroll
  for (int c = 0; c < NC; c++) {
    float v0 = cv[c];
    float v1 = z1v ? cv[c + 17] : 0.0f;
    __half2 h = __floats2half2_rn(v0, v1);
    u[c] = *reinterpret_cast<unsigned*>(&h);
  }
  u[17] = 0u; u[18] = 0u; u[19] = 0u;

  uint4* out = g_spair + (size_t)gcell * 5;
  out[0] = make_uint4(u[0],  u[1],  u[2],  u[3]);
  out[1] = make_uint4(u[4],  u[5],  u[6],  u[7]);
  out[2] = make_uint4(u[8],  u[9],  u[10], u[11]);
  out[3] = make_uint4(u[12], u[13], u[14], u[15]);
  out[4] = make_uint4(u[16], u[17], u[18], u[19]);

  float d0 = __ldg(dens + gcell);
  float d1 = z1v ? __ldg(dens + gcell + 1) : 0.0f;
  g_dpair[gcell] = make_float2(d0, d1);
}

__device__ __forceinline__ void sem_row_zp(const uint4* __restrict__ rp,
                                           float cw0, float cw1, float* acc) {
  uint4 a = __ldg(rp + 0);
  uint4 b = __ldg(rp + 1);
  uint4 c = __ldg(rp + 2);
  uint4 d = __ldg(rp + 3);
  unsigned e = __ldg(reinterpret_cast<const unsigned*>(rp + 4)); // ch16 only
  #define ZACC_(uu, ci)                                          \
    { __half2 hh = *reinterpret_cast<const __half2*>(&(uu));     \
      float2 ff = __half22float2(hh);                            \
      acc[ci] = fmaf(cw0, ff.x, acc[ci]);                        \
      acc[ci] = fmaf(cw1, ff.y, acc[ci]); }
  ZACC_(a.x, 0)  ZACC_(a.y, 1)  ZACC_(a.z, 2)  ZACC_(a.w, 3)
  ZACC_(b.x, 4)  ZACC_(b.y, 5)  ZACC_(b.z, 6)  ZACC_(b.w, 7)
  ZACC_(c.x, 8)  ZACC_(c.y, 9)  ZACC_(c.z, 10) ZACC_(c.w, 11)
  ZACC_(d.x, 12) ZACC_(d.y, 13) ZACC_(d.z, 14) ZACC_(d.w, 15)
  ZACC_(e, 16)
  #undef ZACC_
}

__global__ void __launch_bounds__(256)
nerf_render_kernel(const float* __restrict__ density,
                   const float* __restrict__ semantic,
                   const float* __restrict__ rays,
                   const float* __restrict__ bda,
                   Params P)
{
  __shared__ float sh_t[SMAX];
  const int S = P.S;
  for (int i = threadIdx.x; i < S; i += blockDim.x) {
    double tv;
    if (i < P.n_inner) {
      tv = (2.0 * (double)i + 1.0) / (double)P.n_inner;
    } else {
      int k = i - P.n_inner;
      double step = (1.0 / 64.0 - 1.0) / (double)P.n_outer;
      double l0 = 1.0 + (double)k * step;
      double l1 = (k + 1 == P.n_outer) ? (1.0 / 64.0) : (1.0 + (double)(k + 1) * step);
      tv = 0.5 * (2.0 / l0 + 2.0 / l1);
    }
    sh_t[i] = (float)tv;
  }
  __syncthreads();

  const int lane = threadIdx.x & 31;
  const int warp = (blockIdx.x * blockDim.x + threadIdx.x) >> 5;
  const int total = P.B * P.N;
  if (warp >= total) return;
  const int b = warp / P.N;

  const float* __restrict__ ray = rays + (size_t)warp * 10;
  const float depth = __ldg(ray + 2);
  if (!(depth > 0.0f) || (depth > 52.0f)) return;
  int gt = (int)__ldg(ray + 3);
  gt = min(max(gt, 0), NC - 1);

  float ox = __ldg(ray + 4) / 39.0f;
  float oy = __ldg(ray + 5) / 39.0f;
  float oz = (__ldg(ray + 6) - P.cz) / 39.0f;
  float rdx = __ldg(ray + 7), rdy = __ldg(ray + 8), rdz = __ldg(ray + 9);
  float rn = sqrtf(rdx * rdx + rdy * rdy + rdz * rdz);
  rdx /= rn; rdy /= rn; rdz /= rn;

  const float* __restrict__ bm = bda + (size_t)b * 9;
  const float b00 = __ldg(bm + 0), b01 = __ldg(bm + 1), b02 = __ldg(bm + 2);
  const float b10 = __ldg(bm + 3), b11 = __ldg(bm + 4), b12 = __ldg(bm + 5);
  const float b20 = __ldg(bm + 6), b21 = __ldg(bm + 7), b22 = __ldg(bm + 8);
  const float* __restrict__ dvol = density + (size_t)b * 640000;
  const float* __restrict__ svol = semantic + (size_t)b * 640000 * NC;
  const float2* __restrict__ dpair = g_dpair + (size_t)b * 640000;
  const uint4*  __restrict__ spair = g_spair + (size_t)b * 640000 * 5;

  const float a0_const = 1.0f - __frsqrt_rn(1.0f + expf(P.act_shift));

  float acc[NC];
  #pragma unroll
  for (int c = 0; c < NC; c++) acc[c] = 0.0f;
  float Tcarry = 1.0f, Wc = 0.0f, WMc = 0.0f, cum = 0.0f;
  float prevx = 0.0f, prevy = 0.0f, prevz = 0.0f;
  float bi_acc = 0.0f, w2_acc = 0.0f;
  int pkc = 0;

  const int nch = (S + 31) >> 5;
  for (int ch = 0; ch < nch; ++ch) {
    const int s = (ch << 5) + lane;
    const bool act = s < S;
    const float t = sh_t[act ? s : (S - 1)];

    float px = ox + rdx * t, py = oy + rdy * t, pz = oz + rdz * t;
    float nrm = sqrtf(px * px + py * py + pz * pz);
    const bool inner = nrm <= 1.0f;
    if (!inner) {
      float invn = 1.0f / nrm;
      float scl = (P.one_bg - P.bg * invn) * invn;
      px *= scl; py *= scl; pz *= scl;
    }
    const float qx = b00 * px + b01 * py + b02 * pz;
    const float qy = b10 * px + b11 * py + b12 * pz;
    const float qz = b20 * px + b21 * py + b22 * pz;

    float axp = __shfl_up_sync(FULL, qx, 1);
    float ayp = __shfl_up_sync(FULL, qy, 1);
    float azp = __shfl_up_sync(FULL, qz, 1);
    if (lane == 0) { axp = prevx; ayp = prevy; azp = prevz; }
    float ddx = qx - axp, ddy = qy - ayp, ddz = qz - azp;
    float dd = sqrtf(ddx * ddx + ddy * ddy + ddz * ddz);
    if (!act || s == 0) dd = 0.0f;
    prevx = __shfl_sync(FULL, qx, 31);
    prevy = __shfl_sync(FULL, qy, 31);
    prevz = __shfl_sync(FULL, qz, 31);

    // cumulative-distance reset scan; fast path when every step resets
    bool myover;
    const bool lane_fast = (dd > P.dist_thres) || (!act) || (s == 0);
    if ((cum == 0.0f) && __all_sync(FULL, lane_fast)) {
      myover = dd > P.dist_thres;
    } else {
      unsigned ovm = 0u;
      #pragma unroll
      for (int i = 0; i < 32; i++) {
        float di = __shfl_sync(FULL, dd, i);
        cum += di;
        bool ov = cum > P.dist_thres;
        if (ov) cum = 0.0f;
        ovm |= (ov ? 1u : 0u) << i;
      }
      myover = (ovm >> lane) & 1u;
    }
    const bool keep = act && ((s == 0) ? inner : (inner || myover));

    float gx = (qx - P.xminxy) * P.invrngxy * 199.0f;
    float gy = (qy - P.xminxy) * P.invrngxy * 199.0f;
    float gz = (qz - P.zminf) * P.invrngz * 15.0f;
    float fxg = floorf(gx), fyg = floorf(gy), fzg = floorf(gz);
    int ix = (int)fxg, iy = (int)fyg, iz = (int)fzg;
    float fx = gx - fxg, fy = gy - fyg, fz = gz - fzg;
    const bool inb = (ix >= -1) && (ix < 200) && (iy >= -1) && (iy < 200) &&
                     (iz >= -1) && (iz < 16);

    // z-pair remap: row izc holds (v[izc], v[izc+1]); iz==-1 uses row 0 as the
    // dz=1 corner only (weight fz), matching the reference's validity masking.
    const int   izc = (iz < 0) ? 0 : iz;
    const float wz0 = (iz < 0) ? fz : (1.0f - fz);
    const float wz1 = (iz < 0) ? 0.0f : fz;

    float a = 0.0f;
    if (keep) {
      if (inb) {
        float dens = 0.0f;
        if (P.use_pad) {
          #pragma unroll
          for (int dx = 0; dx < 2; dx++) {
            int X = ix + dx;
            if ((unsigned)X < 200u) {
              float wx = dx ? fx : 1.0f - fx;
              #pragma unroll
              for (int dy = 0; dy < 2; dy++) {
                int Y = iy + dy;
                if ((unsigned)Y < 200u) {
                  float wxy = wx * (dy ? fy : 1.0f - fy);
                  float2 dv = __ldg(dpair + (X * 200 + Y) * 16 + izc);
                  dens += (wxy * wz0) * dv.x;
                  dens += (wxy * wz1) * dv.y;
                }
              }
            }
          }
        } else {
          #pragma unroll
          for (int dx = 0; dx < 2; dx++) {
            int X = ix + dx;
            if ((unsigned)X < 200u) {
              float wx = dx ? fx : 1.0f - fx;
              #pragma unroll
              for (int dy = 0; dy < 2; dy++) {
                int Y = iy + dy;
                if ((unsigned)Y < 200u) {
                  float wxy = wx * (dy ? fy : 1.0f - fy);
                  int base = (X * 200 + Y) * 16;
                  #pragma unroll
                  for (int dz = 0; dz < 2; dz++) {
                    int Z = iz + dz;
                    if ((unsigned)Z < 16u)
                      dens += wxy * (dz ? fz : 1.0f - fz) * __ldg(dvol + base + Z);
                  }
                }
              }
            }
          }
        }
        float e = expf(dens + P.act_shift);
        a = 1.0f - __frsqrt_rn(1.0f + e);
      } else {
        a = a0_const;
      }
      if (!(a > 1e-7f)) a = 0.0f;
    }

    // exclusive transmittance product scan
    float sc_ = 1.0f - a;
    #pragma unroll
    for (int d2 = 1; d2 < 32; d2 <<= 1) {
      float v = __shfl_up_sync(FULL, sc_, d2);
      if (lane >= d2) sc_ *= v;
    }
    float upi = __shfl_up_sync(FULL, sc_, 1);
    float Texcl = Tcarry * ((lane == 0) ? 1.0f : upi);
    float wgt = a * Texcl;
    Tcarry *= __shfl_sync(FULL, sc_, 31);

    bool pk = wgt > 1e-7f;
    float w = pk ? wgt : 0.0f;
    pkc += pk ? 1 : 0;

    // distortion: exclusive cumsums of w, w*m
    float mv = 1.0f - 1.0f / (1.0f + t);
    float wm = w * mv;
    float swv = w, swm = wm;
    #pragma unroll
    for (int d2 = 1; d2 < 32; d2 <<= 1) {
      float v1 = __shfl_up_sync(FULL, swv, d2);
      float v2 = __shfl_up_sync(FULL, swm, d2);
      if (lane >= d2) { swv += v1; swm += v2; }
    }
    float wp  = Wc  + (swv - w);
    float wmp = WMc + (swm - wm);
    Wc  += __shfl_sync(FULL, swv, 31);
    WMc += __shfl_sync(FULL, swm, 31);
    bi_acc += 2.0f * w * (mv * wp - wmp);
    w2_acc += w * w;

    // ---- semantic gather: per-lane, fp16 z-pair rows (5 LDG.128 per tap) ----
    if (w > 0.0f && inb) {
      if (P.use_pad) {
        #pragma unroll
        for (int dx = 0; dx < 2; dx++) {
          int X = ix + dx;
          if ((unsigned)X < 200u) {
            float wx = (dx ? fx : 1.0f - fx) * w;
            #pragma unroll
            for (int dy = 0; dy < 2; dy++) {
              int Y = iy + dy;
              if ((unsigned)Y < 200u) {
                float wxy = wx * (dy ? fy : 1.0f - fy);
                int cell = (X * 200 + Y) * 16 + izc;
                sem_row_zp(spair + (size_t)cell * 5, wxy * wz0, wxy * wz1, acc);
              }
            }
          }
        }
      } else {
        #pragma unroll
        for (int dx = 0; dx < 2; dx++) {
          int X = ix + dx;
          if ((unsigned)X < 200u) {
            float wx = (dx ? fx : 1.0f - fx) * w;
            #pragma unroll
            for (int dy = 0; dy < 2; dy++) {
              int Y = iy + dy;
              if ((unsigned)Y < 200u) {
                float wxy = wx * (dy ? fy : 1.0f - fy);
                int base = (X * 200 + Y) * 16;
                #pragma unroll
                for (int dz = 0; dz < 2; dz++) {
                  int Z = iz + dz;
                  if ((unsigned)Z < 16u) {
                    float cw_ = wxy * (dz ? fz : 1.0f - fz);
                    const float* sp = svol + (size_t)(base + Z) * NC;
                    #pragma unroll
                    for (int c = 0; c < NC; c++)
                      acc[c] = fmaf(cw_, __ldg(sp + c), acc[c]);
                  }
                }
              }
            }
          }
        }
      }
    }
  }

  // warp butterfly reductions
  #pragma unroll
  for (int d2 = 16; d2 > 0; d2 >>= 1) {
    bi_acc += __shfl_xor_sync(FULL, bi_acc, d2);
    w2_acc += __shfl_xor_sync(FULL, w2_acc, d2);
    pkc    += __shfl_xor_sync(FULL, pkc, d2);
    #pragma unroll
    for (int c = 0; c < NC; c++)
      acc[c] += __shfl_xor_sync(FULL, acc[c], d2);
  }

  if (lane == 0) {
    float p = fminf(fmaxf(Tcarry, 1e-6f), 0.999999f);
    float ent = -(p * logf(p) + (1.0f - p) * logf(1.0f - p));

    float mx = acc[0];
    #pragma unroll
    for (int c = 1; c < NC; c++) mx = fmaxf(mx, acc[c]);
    float se = 0.0f;
    #pragma unroll
    for (int c = 0; c < NC; c++) se += expf(acc[c] - mx);
    float agt = acc[0];
    #pragma unroll
    for (int c = 1; c < NC; c++) if (c == gt) agt = acc[c];
    float nll = (mx + logf(se)) - agt;
    float wy = P.cw[gt];

    atomicAdd(&g_wy[b],    (double)wy);
    atomicAdd(&g_wynll[b], (double)wy * (double)nll);
    atomicAdd(&g_ent[b],   (double)ent);
    atomicAdd(&g_bi[b],    (double)bi_acc);
    atomicAdd(&g_w2[b],    (double)w2_acc);
    atomicAdd(&g_pk[b],    (unsigned long long)pkc);
    atomicAdd(&g_nv[b],    1);
  }
}

__global__ void nerf_final_kernel(float* __restrict__ out, int B) {
  if (threadIdx.x == 0 && blockIdx.x == 0) {
    double ls = 0.0, le = 0.0, ld = 0.0;
    for (int b = 0; b < B; b++) {
      double nv = (double)(g_nv[b] > 1 ? g_nv[b] : 1);
      ls += g_wynll[b] / fmax(g_wy[b], 1e-12);
      le += 0.01 * g_ent[b] / nv;
      double nmax = (double)(g_pk[b] > 0ull ? g_pk[b] : 1ull);
      ld += 0.01 * (g_bi[b] + (1.0 / 3.0) * (1.0 / nmax) * g_w2[b]) / nv;
    }
    double invB = 1.0 / (double)B;
    out[0] = (float)(ls * invB);
    out[1] = (float)(le * invB);
    out[2] = (float)(ld * invB);
  }
}

// zero-accumulator fallback when prepass grid is skipped (B > cap)
__global__ void nerf_zero_kernel() {
  if (threadIdx.x < MAXB) {
    int i = threadIdx.x;
    g_wy[i] = 0.0; g_wynll[i] = 0.0; g_ent[i] = 0.0;
    g_bi[i] = 0.0; g_w2[i] = 0.0; g_pk[i] = 0ull; g_nv[i] = 0;
  }
}

extern "C" void kernel_launch(void* const* d_in, const int* in_sizes, int n_in,
                              void* d_out, int out_size) {
  const float* density  = (const float*)d_in[0];
  const float* semantic = (const float*)d_in[1];
  const float* rays     = (const float*)d_in[2];
  const float* bda      = (const float*)d_in[3];

  int B = in_sizes[3] / 9;
  if (B < 1) B = 1;
  if (B > MAXB) B = MAXB;
  int N = in_sizes[2] / (10 * B);

  Params P;
  float bgf = (40.0f - 39.0f) / 39.0f;
  double BG = (double)bgf;
  int n_inner = (int)(2.0 / (2.0 + 2.0 * BG) * 200.0 / 0.5) + 1;
  int n_outer = n_inner / 15;
  P.n_inner = n_inner;
  P.n_outer = n_outer;
  P.S = n_inner + n_outer;
  if (P.S > SMAX) P.S = SMAX;

  P.dist_thres = (float)((2.0 + 2.0 * BG) / 200.0 * 0.5 * 0.95);
  P.act_shift  = (float)log(1.0 / (1.0 - 1e-6) - 1.0);
  P.bg = bgf;
  P.one_bg = (float)(1.0 + BG);

  float xminf = (float)(-1.0 - BG);
  float xmaxf = (float)(1.0 + BG);
  P.xminxy = xminf;
  P.invrngxy = 1.0f / (xmaxf - xminf);

  float rngz32 = 5.4f - (-1.0f);
  float Zf = rngz32 / 80.0f;
  P.zminf = -Zf;
  P.invrngz = 1.0f / (Zf - (-Zf));

  P.cz = (-1.0f + 5.4f) * 0.5f;

  const double freq[NC] = {
    1163161.0, 2309034.0, 188743.0, 2997643.0, 20317180.0, 852476.0,
    243808.0, 2457947.0, 497017.0, 2731022.0, 7224789.0, 214411435.0,
    5565043.0, 63191967.0, 76098082.0, 128860031.0, 141625221.0
  };
  for (int c = 0; c < NC; c++)
    P.cw[c] = (float)(1.0 / log(freq[c] + 0.001));

  P.N = N;
  P.B = B;

  int ncell = B * 640000;
  P.use_pad = (ncell <= PAD_CELL_CAP) ? 1 : 0;
  if (P.use_pad) {
    int ncols = B * 40000;              // (x,y) columns, 16 per block
    nerf_prepass_kernel<<<ncols / 16, 256>>>(semantic, density);
  } else {
    nerf_zero_kernel<<<1, 32>>>();
  }

  long long totalThreads = (long long)B * N * 32;
  int blocks = (int)((totalThreads + 255) / 256);
  nerf_render_kernel<<<blocks, 256>>>(density, semantic, rays, bda, P);

  nerf_final_kernel<<<1, 1>>>((float*)d_out, B);
}

// round 13
// speedup vs baseline: 1.1367x; 1.1367x over previous
#include <cuda_runtime.h>
#include <cuda_fp16.h>
#include <math.h>

#define NC   17
#define MAXB 8
#define FULL 0xffffffffu
#define SMAX 448

// scratch, up to 2 batches of 200*200*16 cells
#define PAD_CELL_CAP (2 * 640000)
// semantic: 24 halves (48B) per cell, halves 0..16 used (ch16 at word 8)
__device__ __align__(16) __half g_spadh[(size_t)PAD_CELL_CAP * 24];
// density: per cell float2(d[z], d[z+1])
__device__ float2 g_dpair[PAD_CELL_CAP];

__device__ double g_wy[MAXB], g_wynll[MAXB], g_ent[MAXB], g_bi[MAXB], g_w2[MAXB];
__device__ unsigned long long g_pk[MAXB];
__device__ int g_nv[MAXB];

struct Params {
  float cw[NC];
  float cz;
  float bg, one_bg;
  float xminxy, invrngxy;
  float zminf, invrngz;
  float dist_thres, act_shift;
  int n_inner, n_outer, S;
  int N, B;
  int use_pad;
};

// Stages 16 (x,y)-columns (16 z * 17 ch = 272 f32 each) through smem with
// float4 loads; emits 48B fp16 rows via fully-coalesced uint4 stores
// (768 contiguous uint4 per block) + float2 density z-pairs.
// grid.x = ncols/16, block = 256.
__global__ void __launch_bounds__(256)
nerf_prepass_kernel(const float* __restrict__ sem,
                    const float* __restrict__ dens) {
  __shared__ float sh[4352];
  const int bid = blockIdx.x, tid = threadIdx.x;
  if (bid == 0 && tid < MAXB) {
    g_wy[tid] = 0.0; g_wynll[tid] = 0.0; g_ent[tid] = 0.0;
    g_bi[tid] = 0.0; g_w2[tid] = 0.0; g_pk[tid] = 0ull; g_nv[tid] = 0;
  }
  const float4* __restrict__ s4 =
      reinterpret_cast<const float4*>(sem + (size_t)bid * 4352);
  float4* sh4 = reinterpret_cast<float4*>(sh);
  #pragma unroll 4
  for (int i = tid; i < 1088; i += 256) sh4[i] = __ldg(s4 + i);
  __syncthreads();

  uint4* outb = reinterpret_cast<uint4*>(g_spadh + (size_t)bid * 256 * 24);
  #pragma unroll
  for (int k = 0; k < 3; k++) {
    int j = tid + k * 256;          // uint4 index within block's 768
    int cell = j / 3;               // local cell 0..255
    int part = j - cell * 3;        // 0,1,2
    int col = cell >> 4, z = cell & 15;
    const float* cv = sh + col * 272 + z * 17;
    uint4 o;
    if (part < 2) {
      int c0 = part * 8;
      __half2 h0 = __floats2half2_rn(cv[c0 + 0], cv[c0 + 1]);
      __half2 h1 = __floats2half2_rn(cv[c0 + 2], cv[c0 + 3]);
      __half2 h2 = __floats2half2_rn(cv[c0 + 4], cv[c0 + 5]);
      __half2 h3 = __floats2half2_rn(cv[c0 + 6], cv[c0 + 7]);
      o = make_uint4(*reinterpret_cast<unsigned*>(&h0),
                     *reinterpret_cast<unsigned*>(&h1),
                     *reinterpret_cast<unsigned*>(&h2),
                     *reinterpret_cast<unsigned*>(&h3));
    } else {
      __half2 h0 = __floats2half2_rn(cv[16], 0.0f);
      o = make_uint4(*reinterpret_cast<unsigned*>(&h0), 0u, 0u, 0u);
    }
    outb[j] = o;
  }

  // density z-pairs: one per cell (256 cells per block, coalesced)
  const int gcell = bid * 256 + tid;
  const int z = tid & 15;
  float d0 = __ldg(dens + gcell);
  float d1 = (z < 15) ? __ldg(dens + gcell + 1) : 0.0f;
  g_dpair[gcell] = make_float2(d0, d1);
}

__device__ __forceinline__ void sem_row_h(const __half* __restrict__ rowp,
                                          float wgt, float* acc) {
  const uint4* p4 = reinterpret_cast<const uint4*>(rowp);
  uint4 ua = __ldg(p4);
  uint4 ub = __ldg(p4 + 1);
  unsigned uc = __ldg(reinterpret_cast<const unsigned*>(rowp) + 8);
  #define ACC2_(uu, i0)                                              \
    { __half2 hh = *reinterpret_cast<const __half2*>(&(uu));         \
      float2 ff = __half22float2(hh);                                \
      acc[i0]     = fmaf(wgt, ff.x, acc[i0]);                        \
      acc[i0 + 1] = fmaf(wgt, ff.y, acc[i0 + 1]); }
  ACC2_(ua.x, 0)  ACC2_(ua.y, 2)  ACC2_(ua.z, 4)  ACC2_(ua.w, 6)
  ACC2_(ub.x, 8)  ACC2_(ub.y, 10) ACC2_(ub.z, 12) ACC2_(ub.w, 14)
  { __half2 hh = *reinterpret_cast<const __half2*>(&uc);
    acc[16] = fmaf(wgt, __low2float(hh), acc[16]); }
  #undef ACC2_
}

__global__ void __launch_bounds__(256)
nerf_render_kernel(const float* __restrict__ density,
                   const float* __restrict__ semantic,
                   const float* __restrict__ rays,
                   const float* __restrict__ bda,
                   Params P)
{
  __shared__ float sh_t[SMAX];
  const int S = P.S;
  for (int i = threadIdx.x; i < S; i += blockDim.x) {
    double tv;
    if (i < P.n_inner) {
      tv = (2.0 * (double)i + 1.0) / (double)P.n_inner;
    } else {
      int k = i - P.n_inner;
      double step = (1.0 / 64.0 - 1.0) / (double)P.n_outer;
      double l0 = 1.0 + (double)k * step;
      double l1 = (k + 1 == P.n_outer) ? (1.0 / 64.0) : (1.0 + (double)(k + 1) * step);
      tv = 0.5 * (2.0 / l0 + 2.0 / l1);
    }
    sh_t[i] = (float)tv;
  }
  __syncthreads();

  const int lane = threadIdx.x & 31;
  const int warp = (blockIdx.x * blockDim.x + threadIdx.x) >> 5;
  const int total = P.B * P.N;
  if (warp >= total) return;
  const int b = warp / P.N;

  const float* __restrict__ ray = rays + (size_t)warp * 10;
  const float depth = __ldg(ray + 2);
  if (!(depth > 0.0f) || (depth > 52.0f)) return;
  int gt = (int)__ldg(ray + 3);
  gt = min(max(gt, 0), NC - 1);

  float ox = __ldg(ray + 4) / 39.0f;
  float oy = __ldg(ray + 5) / 39.0f;
  float oz = (__ldg(ray + 6) - P.cz) / 39.0f;
  float rdx = __ldg(ray + 7), rdy = __ldg(ray + 8), rdz = __ldg(ray + 9);
  float rn = sqrtf(rdx * rdx + rdy * rdy + rdz * rdz);
  rdx /= rn; rdy /= rn; rdz /= rn;

  const float* __restrict__ bm = bda + (size_t)b * 9;
  const float b00 = __ldg(bm + 0), b01 = __ldg(bm + 1), b02 = __ldg(bm + 2);
  const float b10 = __ldg(bm + 3), b11 = __ldg(bm + 4), b12 = __ldg(bm + 5);
  const float b20 = __ldg(bm + 6), b21 = __ldg(bm + 7), b22 = __ldg(bm + 8);
  const float* __restrict__ dvol = density + (size_t)b * 640000;
  const float* __restrict__ svol = semantic + (size_t)b * 640000 * NC;
  const float2* __restrict__ dpair = g_dpair + (size_t)b * 640000;
  const __half* __restrict__ spadh = g_spadh + (size_t)b * 640000 * 24;

  const float a0_const = 1.0f - __frsqrt_rn(1.0f + expf(P.act_shift));

  float acc[NC];
  #pragma unroll
  for (int c = 0; c < NC; c++) acc[c] = 0.0f;
  float Tcarry = 1.0f, Wc = 0.0f, WMc = 0.0f, cum = 0.0f;
  float prevx = 0.0f, prevy = 0.0f, prevz = 0.0f;
  float bi_acc = 0.0f, w2_acc = 0.0f;
  int pkc = 0;

  const int nch = (S + 31) >> 5;
  for (int ch = 0; ch < nch; ++ch) {
    const int s = (ch << 5) + lane;
    const bool act = s < S;
    const float t = sh_t[act ? s : (S - 1)];

    float px = ox + rdx * t, py = oy + rdy * t, pz = oz + rdz * t;
    float nrm = sqrtf(px * px + py * py + pz * pz);
    const bool inner = nrm <= 1.0f;
    if (!inner) {
      float invn = 1.0f / nrm;
      float scl = (P.one_bg - P.bg * invn) * invn;
      px *= scl; py *= scl; pz *= scl;
    }
    const float qx = b00 * px + b01 * py + b02 * pz;
    const float qy = b10 * px + b11 * py + b12 * pz;
    const float qz = b20 * px + b21 * py + b22 * pz;

    float axp = __shfl_up_sync(FULL, qx, 1);
    float ayp = __shfl_up_sync(FULL, qy, 1);
    float azp = __shfl_up_sync(FULL, qz, 1);
    if (lane == 0) { axp = prevx; ayp = prevy; azp = prevz; }
    float ddx = qx - axp, ddy = qy - ayp, ddz = qz - azp;
    float dd = sqrtf(ddx * ddx + ddy * ddy + ddz * ddz);
    if (!act || s == 0) dd = 0.0f;
    prevx = __shfl_sync(FULL, qx, 31);
    prevy = __shfl_sync(FULL, qy, 31);
    prevz = __shfl_sync(FULL, qz, 31);

    // cumulative-distance reset scan; fast path when every step resets
    bool myover;
    const bool lane_fast = (dd > P.dist_thres) || (!act) || (s == 0);
    if ((cum == 0.0f) && __all_sync(FULL, lane_fast)) {
      myover = dd > P.dist_thres;
    } else {
      unsigned ovm = 0u;
      #pragma unroll
      for (int i = 0; i < 32; i++) {
        float di = __shfl_sync(FULL, dd, i);
        cum += di;
        bool ov = cum > P.dist_thres;
        if (ov) cum = 0.0f;
        ovm |= (ov ? 1u : 0u) << i;
      }
      myover = (ovm >> lane) & 1u;
    }
    const bool keep = act && ((s == 0) ? inner : (inner || myover));

    float gx = (qx - P.xminxy) * P.invrngxy * 199.0f;
    float gy = (qy - P.xminxy) * P.invrngxy * 199.0f;
    float gz = (qz - P.zminf) * P.invrngz * 15.0f;
    float fxg = floorf(gx), fyg = floorf(gy), fzg = floorf(gz);
    int ix = (int)fxg, iy = (int)fyg, iz = (int)fzg;
    float fx = gx - fxg, fy = gy - fyg, fz = gz - fzg;
    const bool inb = (ix >= -1) && (ix < 200) && (iy >= -1) && (iy < 200) &&
                     (iz >= -1) && (iz < 16);

    // z remap for the density pair: iz==-1 -> row 0 carries only the dz=1
    // corner (weight fz); otherwise row iz with (1-fz, fz).
    const int   izc = (iz < 0) ? 0 : iz;
    const float wz0 = (iz < 0) ? fz : (1.0f - fz);
    const float wz1 = (iz < 0) ? 0.0f : fz;

    float a = 0.0f;
    if (keep) {
      if (inb) {
        float dens = 0.0f;
        if (P.use_pad) {
          #pragma unroll
          for (int dx = 0; dx < 2; dx++) {
            int X = ix + dx;
            if ((unsigned)X < 200u) {
              float wx = dx ? fx : 1.0f - fx;
              #pragma unroll
              for (int dy = 0; dy < 2; dy++) {
                int Y = iy + dy;
                if ((unsigned)Y < 200u) {
                  float wxy = wx * (dy ? fy : 1.0f - fy);
                  float2 dv = __ldg(dpair + (X * 200 + Y) * 16 + izc);
                  dens += (wxy * wz0) * dv.x;
                  dens += (wxy * wz1) * dv.y;
                }
              }
            }
          }
        } else {
          #pragma unroll
          for (int dx = 0; dx < 2; dx++) {
            int X = ix + dx;
            if ((unsigned)X < 200u) {
              float wx = dx ? fx : 1.0f - fx;
              #pragma unroll
              for (int dy = 0; dy < 2; dy++) {
                int Y = iy + dy;
                if ((unsigned)Y < 200u) {
                  float wxy = wx * (dy ? fy : 1.0f - fy);
                  int base = (X * 200 + Y) * 16;
                  #pragma unroll
                  for (int dz = 0; dz < 2; dz++) {
                    int Z = iz + dz;
                    if ((unsigned)Z < 16u)
                      dens += wxy * (dz ? fz : 1.0f - fz) * __ldg(dvol + base + Z);
                  }
                }
              }
            }
          }
        }
        float e = expf(dens + P.act_shift);
        a = 1.0f - __frsqrt_rn(1.0f + e);
      } else {
        a = a0_const;
      }
      if (!(a > 1e-7f)) a = 0.0f;
    }

    // exclusive transmittance product scan
    float sc_ = 1.0f - a;
    #pragma unroll
    for (int d2 = 1; d2 < 32; d2 <<= 1) {
      float v = __shfl_up_sync(FULL, sc_, d2);
      if (lane >= d2) sc_ *= v;
    }
    float upi = __shfl_up_sync(FULL, sc_, 1);
    float Texcl = Tcarry * ((lane == 0) ? 1.0f : upi);
    float wgt = a * Texcl;
    Tcarry *= __shfl_sync(FULL, sc_, 31);

    bool pk = wgt > 1e-7f;
    float w = pk ? wgt : 0.0f;
    pkc += pk ? 1 : 0;

    // distortion: exclusive cumsums of w, w*m
    float mv = 1.0f - 1.0f / (1.0f + t);
    float wm = w * mv;
    float swv = w, swm = wm;
    #pragma unroll
    for (int d2 = 1; d2 < 32; d2 <<= 1) {
      float v1 = __shfl_up_sync(FULL, swv, d2);
      float v2 = __shfl_up_sync(FULL, swm, d2);
      if (lane >= d2) { swv += v1; swm += v2; }
    }
    float wp  = Wc  + (swv - w);
    float wmp = WMc + (swm - wm);
    Wc  += __shfl_sync(FULL, swv, 31);
    WMc += __shfl_sync(FULL, swm, 31);
    bi_acc += 2.0f * w * (mv * wp - wmp);
    w2_acc += w * w;

    // ---- semantic gather: per-lane, fp16 48B rows (R10 layout) ----
    if (w > 0.0f && inb) {
      if (P.use_pad) {
        const bool z0ok = iz >= 0;
        const bool z1ok = iz < 15;
        const float fz0 = 1.0f - fz;
        #pragma unroll
        for (int dx = 0; dx < 2; dx++) {
          int X = ix + dx;
          if ((unsigned)X < 200u) {
            float wx = (dx ? fx : 1.0f - fx) * w;
            #pragma unroll
            for (int dy = 0; dy < 2; dy++) {
              int Y = iy + dy;
              if ((unsigned)Y < 200u) {
                float wxy = wx * (dy ? fy : 1.0f - fy);
                int cell = (X * 200 + Y) * 16 + iz;
                if (z0ok) sem_row_h(spadh + (size_t)cell * 24, wxy * fz0, acc);
                if (z1ok) sem_row_h(spadh + (size_t)(cell + 1) * 24, wxy * fz, acc);
              }
            }
          }
        }
      } else {
        #pragma unroll
        for (int dx = 0; dx < 2; dx++) {
          int X = ix + dx;
          if ((unsigned)X < 200u) {
            float wx = (dx ? fx : 1.0f - fx) * w;
            #pragma unroll
            for (int dy = 0; dy < 2; dy++) {
              int Y = iy + dy;
              if ((unsigned)Y < 200u) {
                float wxy = wx * (dy ? fy : 1.0f - fy);
                int base = (X * 200 + Y) * 16;
                #pragma unroll
                for (int dz = 0; dz < 2; dz++) {
                  int Z = iz + dz;
                  if ((unsigned)Z < 16u) {
                    float cw_ = wxy * (dz ? fz : 1.0f - fz);
                    const float* sp = svol + (size_t)(base + Z) * NC;
                    #pragma unroll
                    for (int c = 0; c < NC; c++)
                      acc[c] = fmaf(cw_, __ldg(sp + c), acc[c]);
                  }
                }
              }
            }
          }
        }
      }
    }
  }

  // warp butterfly reductions
  #pragma unroll
  for (int d2 = 16; d2 > 0; d2 >>= 1) {
    bi_acc += __shfl_xor_sync(FULL, bi_acc, d2);
    w2_acc += __shfl_xor_sync(FULL, w2_acc, d2);
    pkc    += __shfl_xor_sync(FULL, pkc, d2);
    #pragma unroll
    for (int c = 0; c < NC; c++)
      acc[c] += __shfl_xor_sync(FULL, acc[c], d2);
  }

  if (lane == 0) {
    float p = fminf(fmaxf(Tcarry, 1e-6f), 0.999999f);
    float ent = -(p * logf(p) + (1.0f - p) * logf(1.0f - p));

    float mx = acc[0];
    #pragma unroll
    for (int c = 1; c < NC; c++) mx = fmaxf(mx, acc[c]);
    float se = 0.0f;
    #pragma unroll
    for (int c = 0; c < NC; c++) se += expf(acc[c] - mx);
    float agt = acc[0];
    #pragma unroll
    for (int c = 1; c < NC; c++) if (c == gt) agt = acc[c];
    float nll = (mx + logf(se)) - agt;
    float wy = P.cw[gt];

    atomicAdd(&g_wy[b],    (double)wy);
    atomicAdd(&g_wynll[b], (double)wy * (double)nll);
    atomicAdd(&g_ent[b],   (double)ent);
    atomicAdd(&g_bi[b],    (double)bi_acc);
    atomicAdd(&g_w2[b],    (double)w2_acc);
    atomicAdd(&g_pk[b],    (unsigned long long)pkc);
    atomicAdd(&g_nv[b],    1);
  }
}

__global__ void nerf_final_kernel(float* __restrict__ out, int B) {
  if (threadIdx.x == 0 && blockIdx.x == 0) {
    double ls = 0.0, le = 0.0, ld = 0.0;
    for (int b = 0; b < B; b++) {
      double nv = (double)(g_nv[b] > 1 ? g_nv[b] : 1);
      ls += g_wynll[b] / fmax(g_wy[b], 1e-12);
      le += 0.01 * g_ent[b] / nv;
      double nmax = (double)(g_pk[b] > 0ull ? g_pk[b] : 1ull);
      ld += 0.01 * (g_bi[b] + (1.0 / 3.0) * (1.0 / nmax) * g_w2[b]) / nv;
    }
    double invB = 1.0 / (double)B;
    out[0] = (float)(ls * invB);
    out[1] = (float)(le * invB);
    out[2] = (float)(ld * invB);
  }
}

// zero-accumulator fallback when prepass is skipped (B > cap)
__global__ void nerf_zero_kernel() {
  if (threadIdx.x < MAXB) {
    int i = threadIdx.x;
    g_wy[i] = 0.0; g_wynll[i] = 0.0; g_ent[i] = 0.0;
    g_bi[i] = 0.0; g_w2[i] = 0.0; g_pk[i] = 0ull; g_nv[i] = 0;
  }
}

extern "C" void kernel_launch(void* const* d_in, const int* in_sizes, int n_in,
                              void* d_out, int out_size) {
  const float* density  = (const float*)d_in[0];
  const float* semantic = (const float*)d_in[1];
  const float* rays     = (const float*)d_in[2];
  const float* bda      = (const float*)d_in[3];

  int B = in_sizes[3] / 9;
  if (B < 1) B = 1;
  if (B > MAXB) B = MAXB;
  int N = in_sizes[2] / (10 * B);

  Params P;
  float bgf = (40.0f - 39.0f) / 39.0f;
  double BG = (double)bgf;
  int n_inner = (int)(2.0 / (2.0 + 2.0 * BG) * 200.0 / 0.5) + 1;
  int n_outer = n_inner / 15;
  P.n_inner = n_inner;
  P.n_outer = n_outer;
  P.S = n_inner + n_outer;
  if (P.S > SMAX) P.S = SMAX;

  P.dist_thres = (float)((2.0 + 2.0 * BG) / 200.0 * 0.5 * 0.95);
  P.act_shift  = (float)log(1.0 / (1.0 - 1e-6) - 1.0);
  P.bg = bgf;
  P.one_bg = (float)(1.0 + BG);

  float xminf = (float)(-1.0 - BG);
  float xmaxf = (float)(1.0 + BG);
  P.xminxy = xminf;
  P.invrngxy = 1.0f / (xmaxf - xminf);

  float rngz32 = 5.4f - (-1.0f);
  float Zf = rngz32 / 80.0f;
  P.zminf = -Zf;
  P.invrngz = 1.0f / (Zf - (-Zf));

  P.cz = (-1.0f + 5.4f) * 0.5f;

  const double freq[NC] = {
    1163161.0, 2309034.0, 188743.0, 2997643.0, 20317180.0, 852476.0,
    243808.0, 2457947.0, 497017.0, 2731022.0, 7224789.0, 214411435.0,
    5565043.0, 63191967.0, 76098082.0, 128860031.0, 141625221.0
  };
  for (int c = 0; c < NC; c++)
    P.cw[c] = (float)(1.0 / log(freq[c] + 0.001));

  P.N = N;
  P.B = B;

  int ncell = B * 640000;
  P.use_pad = (ncell <= PAD_CELL_CAP) ? 1 : 0;
  if (P.use_pad) {
    int ncols = B * 40000;              // 16 (x,y)-columns per block
    nerf_prepass_kernel<<<ncols / 16, 256>>>(semantic, density);
  } else {
    nerf_zero_kernel<<<1, 32>>>();
  }

  long long totalThreads = (long long)B * N * 32;
  int blocks = (int)((totalThreads + 255) / 256);
  nerf_render_kernel<<<blocks, 256>>>(density, semantic, rays, bda, P);

  nerf_final_kernel<<<1, 1>>>((float*)d_out, B);
}

// round 17
// speedup vs baseline: 1.1512x; 1.0127x over previous
#include <cuda_runtime.h>
#include <cuda_fp16.h>
#include <math.h>

#define NC   17
#define MAXB 8
#define FULL 0xffffffffu
#define SMAX 448

// merged scratch, up to 2 batches of 200*200*16 cells.
// Per cell: 3 x uint4 (48B):
//   uint4 0: ch0-7  as 4 x half2
//   uint4 1: ch8-15 as 4 x half2
//   uint4 2: .x = half2(ch16, 0), .y = 0, .z = bits(d[z]), .w = bits(d[z+1])
#define PAD_CELL_CAP (2 * 640000)
__device__ uint4 g_srow[(size_t)PAD_CELL_CAP * 3];

__device__ double g_wy[MAXB], g_wynll[MAXB], g_ent[MAXB], g_bi[MAXB], g_w2[MAXB];
__device__ unsigned long long g_pk[MAXB];
__device__ int g_nv[MAXB];

struct Params {
  float cw[NC];
  float cz;
  float bg, one_bg;
  float xminxy, invrngxy;
  float zminf, invrngz;
  float dist_thres, act_shift;
  int n_inner, n_outer, S;
  int N, B;
  int use_pad;
};

// Stages 16 (x,y)-columns (16 z * 17 ch = 272 f32 each) through smem with
// float4 loads; emits merged 48B rows via fully-coalesced uint4 stores
// (768 contiguous uint4 per block). Density pair rides in row part 2.
// grid.x = ncols/16, block = 256.
__global__ void __launch_bounds__(256)
nerf_prepass_kernel(const float* __restrict__ sem,
                    const float* __restrict__ dens) {
  __shared__ float sh[4352];
  const int bid = blockIdx.x, tid = threadIdx.x;
  if (bid == 0 && tid < MAXB) {
    g_wy[tid] = 0.0; g_wynll[tid] = 0.0; g_ent[tid] = 0.0;
    g_bi[tid] = 0.0; g_w2[tid] = 0.0; g_pk[tid] = 0ull; g_nv[tid] = 0;
  }
  const float4* __restrict__ s4 =
      reinterpret_cast<const float4*>(sem + (size_t)bid * 4352);
  float4* sh4 = reinterpret_cast<float4*>(sh);
  #pragma unroll 4
  for (int i = tid; i < 1088; i += 256) sh4[i] = __ldg(s4 + i);
  __syncthreads();

  uint4* outb = g_srow + (size_t)bid * 256 * 3;
  #pragma unroll
  for (int k = 0; k < 3; k++) {
    int j = tid + k * 256;          // uint4 index within block's 768
    int cell = j / 3;               // local cell 0..255
    int part = j - cell * 3;        // 0,1,2
    int col = cell >> 4, z = cell & 15;
    const float* cv = sh + col * 272 + z * 17;
    uint4 o;
    if (part < 2) {
      int c0 = part * 8;
      __half2 h0 = __floats2half2_rn(cv[c0 + 0], cv[c0 + 1]);
      __half2 h1 = __floats2half2_rn(cv[c0 + 2], cv[c0 + 3]);
      __half2 h2 = __floats2half2_rn(cv[c0 + 4], cv[c0 + 5]);
      __half2 h3 = __floats2half2_rn(cv[c0 + 6], cv[c0 + 7]);
      o = make_uint4(*reinterpret_cast<unsigned*>(&h0),
                     *reinterpret_cast<unsigned*>(&h1),
                     *reinterpret_cast<unsigned*>(&h2),
                     *reinterpret_cast<unsigned*>(&h3));
    } else {
      int gcell = bid * 256 + cell;
      __half2 h0 = __floats2half2_rn(cv[16], 0.0f);
      float d0 = __ldg(dens + gcell);
      float d1 = (z < 15) ? __ldg(dens + gcell + 1) : 0.0f;
      o = make_uint4(*reinterpret_cast<unsigned*>(&h0), 0u,
                     __float_as_uint(d0), __float_as_uint(d1));
    }
    outb[j] = o;
  }
}

__device__ __forceinline__ void sem_row_h(const uint4* __restrict__ rp,
                                          float wgt, float* acc) {
  uint4 ua = __ldg(rp);
  uint4 ub = __ldg(rp + 1);
  unsigned uc = __ldg(reinterpret_cast<const unsigned*>(rp + 2)); // ch16 half2
  #define ACC2_(uu, i0)                                              \
    { __half2 hh = *reinterpret_cast<const __half2*>(&(uu));         \
      float2 ff = __half22float2(hh);                                \
      acc[i0]     = fmaf(wgt, ff.x, acc[i0]);                        \
      acc[i0 + 1] = fmaf(wgt, ff.y, acc[i0 + 1]); }
  ACC2_(ua.x, 0)  ACC2_(ua.y, 2)  ACC2_(ua.z, 4)  ACC2_(ua.w, 6)
  ACC2_(ub.x, 8)  ACC2_(ub.y, 10) ACC2_(ub.z, 12) ACC2_(ub.w, 14)
  { __half2 hh = *reinterpret_cast<const __half2*>(&uc);
    acc[16] = fmaf(wgt, __low2float(hh), acc[16]); }
  #undef ACC2_
}

__global__ void __launch_bounds__(256)
nerf_render_kernel(const float* __restrict__ density,
                   const float* __restrict__ semantic,
                   const float* __restrict__ rays,
                   const float* __restrict__ bda,
                   Params P)
{
  __shared__ float sh_t[SMAX];
  const int S = P.S;
  for (int i = threadIdx.x; i < S; i += blockDim.x) {
    double tv;
    if (i < P.n_inner) {
      tv = (2.0 * (double)i + 1.0) / (double)P.n_inner;
    } else {
      int k = i - P.n_inner;
      double step = (1.0 / 64.0 - 1.0) / (double)P.n_outer;
      double l0 = 1.0 + (double)k * step;
      double l1 = (k + 1 == P.n_outer) ? (1.0 / 64.0) : (1.0 + (double)(k + 1) * step);
      tv = 0.5 * (2.0 / l0 + 2.0 / l1);
    }
    sh_t[i] = (float)tv;
  }
  __syncthreads();

  const int lane = threadIdx.x & 31;
  const int warp = (blockIdx.x * blockDim.x + threadIdx.x) >> 5;
  const int total = P.B * P.N;
  if (warp >= total) return;
  const int b = warp / P.N;

  const float* __restrict__ ray = rays + (size_t)warp * 10;
  const float depth = __ldg(ray + 2);
  if (!(depth > 0.0f) || (depth > 52.0f)) return;
  int gt = (int)__ldg(ray + 3);
  gt = min(max(gt, 0), NC - 1);

  float ox = __ldg(ray + 4) / 39.0f;
  float oy = __ldg(ray + 5) / 39.0f;
  float oz = (__ldg(ray + 6) - P.cz) / 39.0f;
  float rdx = __ldg(ray + 7), rdy = __ldg(ray + 8), rdz = __ldg(ray + 9);
  float rn = sqrtf(rdx * rdx + rdy * rdy + rdz * rdz);
  rdx /= rn; rdy /= rn; rdz /= rn;

  const float* __restrict__ bm = bda + (size_t)b * 9;
  const float b00 = __ldg(bm + 0), b01 = __ldg(bm + 1), b02 = __ldg(bm + 2);
  const float b10 = __ldg(bm + 3), b11 = __ldg(bm + 4), b12 = __ldg(bm + 5);
  const float b20 = __ldg(bm + 6), b21 = __ldg(bm + 7), b22 = __ldg(bm + 8);
  const float* __restrict__ dvol = density + (size_t)b * 640000;
  const float* __restrict__ svol = semantic + (size_t)b * 640000 * NC;
  const uint4* __restrict__ srow = g_srow + (size_t)b * 640000 * 3;

  const float a0_const = 1.0f - __frsqrt_rn(1.0f + expf(P.act_shift));

  float acc[NC];
  #pragma unroll
  for (int c = 0; c < NC; c++) acc[c] = 0.0f;
  float Tcarry = 1.0f, Wc = 0.0f, WMc = 0.0f, cum = 0.0f;
  float prevx = 0.0f, prevy = 0.0f, prevz = 0.0f;
  float bi_acc = 0.0f, w2_acc = 0.0f;
  int pkc = 0;

  const int nch = (S + 31) >> 5;
  for (int ch = 0; ch < nch; ++ch) {
    const int s = (ch << 5) + lane;
    const bool act = s < S;
    const float t = sh_t[act ? s : (S - 1)];

    float px = ox + rdx * t, py = oy + rdy * t, pz = oz + rdz * t;
    float nrm = sqrtf(px * px + py * py + pz * pz);
    const bool inner = nrm <= 1.0f;
    if (!inner) {
      float invn = 1.0f / nrm;
      float scl = (P.one_bg - P.bg * invn) * invn;
      px *= scl; py *= scl; pz *= scl;
    }
    const float qx = b00 * px + b01 * py + b02 * pz;
    const float qy = b10 * px + b11 * py + b12 * pz;
    const float qz = b20 * px + b21 * py + b22 * pz;

    float axp = __shfl_up_sync(FULL, qx, 1);
    float ayp = __shfl_up_sync(FULL, qy, 1);
    float azp = __shfl_up_sync(FULL, qz, 1);
    if (lane == 0) { axp = prevx; ayp = prevy; azp = prevz; }
    float ddx = qx - axp, ddy = qy - ayp, ddz = qz - azp;
    float dd = sqrtf(ddx * ddx + ddy * ddy + ddz * ddz);
    if (!act || s == 0) dd = 0.0f;
    prevx = __shfl_sync(FULL, qx, 31);
    prevy = __shfl_sync(FULL, qy, 31);
    prevz = __shfl_sync(FULL, qz, 31);

    // cumulative-distance reset scan; fast path when every step resets
    bool myover;
    const bool lane_fast = (dd > P.dist_thres) || (!act) || (s == 0);
    if ((cum == 0.0f) && __all_sync(FULL, lane_fast)) {
      myover = dd > P.dist_thres;
    } else {
      unsigned ovm = 0u;
      #pragma unroll
      for (int i = 0; i < 32; i++) {
        float di = __shfl_sync(FULL, dd, i);
        cum += di;
        bool ov = cum > P.dist_thres;
        if (ov) cum = 0.0f;
        ovm |= (ov ? 1u : 0u) << i;
      }
      myover = (ovm >> lane) & 1u;
    }
    const bool keep = act && ((s == 0) ? inner : (inner || myover));

    float gx = (qx - P.xminxy) * P.invrngxy * 199.0f;
    float gy = (qy - P.xminxy) * P.invrngxy * 199.0f;
    float gz = (qz - P.zminf) * P.invrngz * 15.0f;
    float fxg = floorf(gx), fyg = floorf(gy), fzg = floorf(gz);
    int ix = (int)fxg, iy = (int)fyg, iz = (int)fzg;
    float fx = gx - fxg, fy = gy - fyg, fz = gz - fzg;
    const bool inb = (ix >= -1) && (ix < 200) && (iy >= -1) && (iy < 200) &&
                     (iz >= -1) && (iz < 16);

    // z remap for the density pair: iz==-1 -> row 0 carries only the dz=1
    // corner (weight fz); otherwise row iz with (1-fz, fz).
    const int   izc = (iz < 0) ? 0 : iz;
    const float wz0 = (iz < 0) ? fz : (1.0f - fz);
    const float wz1 = (iz < 0) ? 0.0f : fz;

    float a = 0.0f;
    if (keep) {
      if (inb) {
        float dens = 0.0f;
        if (P.use_pad) {
          // density pair lives in row uint4 #2 (.z,.w) -> also warms the row
          // line for the semantic phase below.
          #pragma unroll
          for (int dx = 0; dx < 2; dx++) {
            int X = ix + dx;
            if ((unsigned)X < 200u) {
              float wx = dx ? fx : 1.0f - fx;
              #pragma unroll
              for (int dy = 0; dy < 2; dy++) {
                int Y = iy + dy;
                if ((unsigned)Y < 200u) {
                  float wxy = wx * (dy ? fy : 1.0f - fy);
                  uint4 u2 = __ldg(srow + (size_t)((X * 200 + Y) * 16 + izc) * 3 + 2);
                  dens += (wxy * wz0) * __uint_as_float(u2.z);
                  dens += (wxy * wz1) * __uint_as_float(u2.w);
                }
              }
            }
          }
        } else {
          #pragma unroll
          for (int dx = 0; dx < 2; dx++) {
            int X = ix + dx;
            if ((unsigned)X < 200u) {
              float wx = dx ? fx : 1.0f - fx;
              #pragma unroll
              for (int dy = 0; dy < 2; dy++) {
                int Y = iy + dy;
                if ((unsigned)Y < 200u) {
                  float wxy = wx * (dy ? fy : 1.0f - fy);
                  int base = (X * 200 + Y) * 16;
                  #pragma unroll
                  for (int dz = 0; dz < 2; dz++) {
                    int Z = iz + dz;
                    if ((unsigned)Z < 16u)
                      dens += wxy * (dz ? fz : 1.0f - fz) * __ldg(dvol + base + Z);
                  }
                }
              }
            }
          }
        }
        float e = expf(dens + P.act_shift);
        a = 1.0f - __frsqrt_rn(1.0f + e);
      } else {
        a = a0_const;
      }
      if (!(a > 1e-7f)) a = 0.0f;
    }

    // exclusive transmittance product scan
    float sc_ = 1.0f - a;
    #pragma unroll
    for (int d2 = 1; d2 < 32; d2 <<= 1) {
      float v = __shfl_up_sync(FULL, sc_, d2);
      if (lane >= d2) sc_ *= v;
    }
    float upi = __shfl_up_sync(FULL, sc_, 1);
    float Texcl = Tcarry * ((lane == 0) ? 1.0f : upi);
    float wgt = a * Texcl;
    Tcarry *= __shfl_sync(FULL, sc_, 31);

    bool pk = wgt > 1e-7f;
    float w = pk ? wgt : 0.0f;
    pkc += pk ? 1 : 0;

    // distortion: exclusive cumsums of w, w*m
    float mv = 1.0f - 1.0f / (1.0f + t);
    float wm = w * mv;
    float swv = w, swm = wm;
    #pragma unroll
    for (int d2 = 1; d2 < 32; d2 <<= 1) {
      float v1 = __shfl_up_sync(FULL, swv, d2);
      float v2 = __shfl_up_sync(FULL, swm, d2);
      if (lane >= d2) { swv += v1; swm += v2; }
    }
    float wp  = Wc  + (swv - w);
    float wmp = WMc + (swm - wm);
    Wc  += __shfl_sync(FULL, swv, 31);
    WMc += __shfl_sync(FULL, swm, 31);
    bi_acc += 2.0f * w * (mv * wp - wmp);
    w2_acc += w * w;

    // ---- semantic gather: per-lane, merged 48B rows; z0 row is L1-warm ----
    if (w > 0.0f && inb) {
      if (P.use_pad) {
        const bool z0ok = iz >= 0;
        const bool z1ok = iz < 15;
        const float fz0 = 1.0f - fz;
        #pragma unroll
        for (int dx = 0; dx < 2; dx++) {
          int X = ix + dx;
          if ((unsigned)X < 200u) {
            float wx = (dx ? fx : 1.0f - fx) * w;
            #pragma unroll
            for (int dy = 0; dy < 2; dy++) {
              int Y = iy + dy;
              if ((unsigned)Y < 200u) {
                float wxy = wx * (dy ? fy : 1.0f - fy);
                int cell = (X * 200 + Y) * 16 + iz;
                if (z0ok) sem_row_h(srow + (size_t)cell * 3, wxy * fz0, acc);
                if (z1ok) sem_row_h(srow + (size_t)(cell + 1) * 3, wxy * fz, acc);
              }
            }
          }
        }
      } else {
        #pragma unroll
        for (int dx = 0; dx < 2; dx++) {
          int X = ix + dx;
          if ((unsigned)X < 200u) {
            float wx = (dx ? fx : 1.0f - fx) * w;
            #pragma unroll
            for (int dy = 0; dy < 2; dy++) {
              int Y = iy + dy;
              if ((unsigned)Y < 200u) {
                float wxy = wx * (dy ? fy : 1.0f - fy);
                int base = (X * 200 + Y) * 16;
                #pragma unroll
                for (int dz = 0; dz < 2; dz++) {
                  int Z = iz + dz;
                  if ((unsigned)Z < 16u) {
                    float cw_ = wxy * (dz ? fz : 1.0f - fz);
                    const float* sp = svol + (size_t)(base + Z) * NC;
                    #pragma unroll
                    for (int c = 0; c < NC; c++)
                      acc[c] = fmaf(cw_, __ldg(sp + c), acc[c]);
                  }
                }
              }
            }
          }
        }
      }
    }
  }

  // warp butterfly reductions
  #pragma unroll
  for (int d2 = 16; d2 > 0; d2 >>= 1) {
    bi_acc += __shfl_xor_sync(FULL, bi_acc, d2);
    w2_acc += __shfl_xor_sync(FULL, w2_acc, d2);
    pkc    += __shfl_xor_sync(FULL, pkc, d2);
    #pragma unroll
    for (int c = 0; c < NC; c++)
      acc[c] += __shfl_xor_sync(FULL, acc[c], d2);
  }

  if (lane == 0) {
    float p = fminf(fmaxf(Tcarry, 1e-6f), 0.999999f);
    float ent = -(p * logf(p) + (1.0f - p) * logf(1.0f - p));

    float mx = acc[0];
    #pragma unroll
    for (int c = 1; c < NC; c++) mx = fmaxf(mx, acc[c]);
    float se = 0.0f;
    #pragma unroll
    for (int c = 0; c < NC; c++) se += expf(acc[c] - mx);
    float agt = acc[0];
    #pragma unroll
    for (int c = 1; c < NC; c++) if (c == gt) agt = acc[c];
    float nll = (mx + logf(se)) - agt;
    float wy = P.cw[gt];

    atomicAdd(&g_wy[b],    (double)wy);
    atomicAdd(&g_wynll[b], (double)wy * (double)nll);
    atomicAdd(&g_ent[b],   (double)ent);
    atomicAdd(&g_bi[b],    (double)bi_acc);
    atomicAdd(&g_w2[b],    (double)w2_acc);
    atomicAdd(&g_pk[b],    (unsigned long long)pkc);
    atomicAdd(&g_nv[b],    1);
  }
}

__global__ void nerf_final_kernel(float* __restrict__ out, int B) {
  if (threadIdx.x == 0 && blockIdx.x == 0) {
    double ls = 0.0, le = 0.0, ld = 0.0;
    for (int b = 0; b < B; b++) {
      double nv = (double)(g_nv[b] > 1 ? g_nv[b] : 1);
      ls += g_wynll[b] / fmax(g_wy[b], 1e-12);
      le += 0.01 * g_ent[b] / nv;
      double nmax = (double)(g_pk[b] > 0ull ? g_pk[b] : 1ull);
      ld += 0.01 * (g_bi[b] + (1.0 / 3.0) * (1.0 / nmax) * g_w2[b]) / nv;
    }
    double invB = 1.0 / (double)B;
    out[0] = (float)(ls * invB);
    out[1] = (float)(le * invB);
    out[2] = (float)(ld * invB);
  }
}

// zero-accumulator fallback when prepass is skipped (B > cap)
__global__ void nerf_zero_kernel() {
  if (threadIdx.x < MAXB) {
    int i = threadIdx.x;
    g_wy[i] = 0.0; g_wynll[i] = 0.0; g_ent[i] = 0.0;
    g_bi[i] = 0.0; g_w2[i] = 0.0; g_pk[i] = 0ull; g_nv[i] = 0;
  }
}

extern "C" void kernel_launch(void* const* d_in, const int* in_sizes, int n_in,
                              void* d_out, int out_size) {
  const float* density  = (const float*)d_in[0];
  const float* semantic = (const float*)d_in[1];
  const float* rays     = (const float*)d_in[2];
  const float* bda      = (const float*)d_in[3];

  int B = in_sizes[3] / 9;
  if (B < 1) B = 1;
  if (B > MAXB) B = MAXB;
  int N = in_sizes[2] / (10 * B);

  Params P;
  float bgf = (40.0f - 39.0f) / 39.0f;
  double BG = (double)bgf;
  int n_inner = (int)(2.0 / (2.0 + 2.0 * BG) * 200.0 / 0.5) + 1;
  int n_outer = n_inner / 15;
  P.n_inner = n_inner;
  P.n_outer = n_outer;
  P.S = n_inner + n_outer;
  if (P.S > SMAX) P.S = SMAX;

  P.dist_thres = (float)((2.0 + 2.0 * BG) / 200.0 * 0.5 * 0.95);
  P.act_shift  = (float)log(1.0 / (1.0 - 1e-6) - 1.0);
  P.bg = bgf;
  P.one_bg = (float)(1.0 + BG);

  float xminf = (float)(-1.0 - BG);
  float xmaxf = (float)(1.0 + BG);
  P.xminxy = xminf;
  P.invrngxy = 1.0f / (xmaxf - xminf);

  float rngz32 = 5.4f - (-1.0f);
  float Zf = rngz32 / 80.0f;
  P.zminf = -Zf;
  P.invrngz = 1.0f / (Zf - (-Zf));

  P.cz = (-1.0f + 5.4f) * 0.5f;

  const double freq[NC] = {
    1163161.0, 2309034.0, 188743.0, 2997643.0, 20317180.0, 852476.0,
    243808.0, 2457947.0, 497017.0, 2731022.0, 7224789.0, 214411435.0,
    5565043.0, 63191967.0, 76098082.0, 128860031.0, 141625221.0
  };
  for (int c = 0; c < NC; c++)
    P.cw[c] = (float)(1.0 / log(freq[c] + 0.001));

  P.N = N;
  P.B = B;

  int ncell = B * 640000;
  P.use_pad = (ncell <= PAD_CELL_CAP) ? 1 : 0;
  if (P.use_pad) {
    int ncols = B * 40000;              // 16 (x,y)-columns per block
    nerf_prepass_kernel<<<ncols / 16, 256>>>(semantic, density);
  } else {
    nerf_zero_kernel<<<1, 32>>>();
  }

  long long totalThreads = (long long)B * N * 32;
  int blocks = (int)((totalThreads + 255) / 256);
  nerf_render_kernel<<<blocks, 256>>>(density, semantic, rays, bda, P);

  nerf_final_kernel<<<1, 1>>>((float*)d_out, B);
}